// round 1
// baseline (speedup 1.0000x reference)
#include <cuda_runtime.h>
#include <math.h>

#define N_WIRES 8
#define NROWS   32768      // B*S = 16*2048
#define FFN     2048
#define EMB     512

// Scratch (static device globals per allocation rules)
__device__ float g_EV[NROWS * N_WIRES];               // 1 MB
__device__ float g_H[(size_t)NROWS * FFN];            // 268 MB
__device__ float g_W2T[FFN * EMB];                    // 4 MB

// ---------------------------------------------------------------------------
// Kernel 1: quantum circuit collapsed to closed form.
// z_i = A_i*cos(x_i) - C_i*sin(x_i),
//   A_i = cos a cos c + sin a sin b sin c,  C_i = cos b sin c
// ev_0 = z1..z7 ; ev_k = z0..zk (k>=1)   [CNOT ring is Clifford -> Z strings]
// ---------------------------------------------------------------------------
__global__ void ev_kernel(const float* __restrict__ x,
                          const float* __restrict__ params) {
    int row = blockIdx.x * blockDim.x + threadIdx.x;
    if (row >= NROWS) return;
    float z[8];
#pragma unroll
    for (int i = 0; i < 8; i++) {
        float a = params[i * 3 + 0];
        float b = params[i * 3 + 1];
        float c = params[i * 3 + 2];
        float sa, ca, sb, cb, sc, cc;
        sincosf(a, &sa, &ca);
        sincosf(b, &sb, &cb);
        sincosf(c, &sc, &cc);
        float Acoef = ca * cc + sa * sb * sc;
        float Ccoef = cb * sc;
        float xv = x[row * 8 + i];
        float sx, cx;
        sincosf(xv, &sx, &cx);
        z[i] = Acoef * cx - Ccoef * sx;
    }
    float ev[8];
    float pre = z[0];
#pragma unroll
    for (int k = 1; k < 8; k++) { pre *= z[k]; ev[k] = pre; }
    float suf = 1.0f;
#pragma unroll
    for (int k = 7; k >= 1; k--) suf *= z[k];
    ev[0] = suf;

    float4* out = (float4*)&g_EV[row * 8];
    out[0] = make_float4(ev[0], ev[1], ev[2], ev[3]);
    out[1] = make_float4(ev[4], ev[5], ev[6], ev[7]);
}

// ---------------------------------------------------------------------------
// Kernel 2: H = relu(EV @ W1^T + b1)   (memory-bound; 8-wide dot per element)
// ---------------------------------------------------------------------------
__global__ void h_kernel(const float* __restrict__ W1,
                         const float* __restrict__ b1) {
    int idx = blockIdx.x * blockDim.x + threadIdx.x;   // [0, NROWS*FFN)
    int row = idx >> 11;
    int c   = idx & (FFN - 1);
    const float4* e = (const float4*)&g_EV[row * 8];
    float4 e0 = e[0], e1 = e[1];
    const float4* w = (const float4*)&W1[c * 8];
    float4 w0 = w[0], w1 = w[1];
    float h = b1[c];
    h += e0.x * w0.x + e0.y * w0.y + e0.z * w0.z + e0.w * w0.w;
    h += e1.x * w1.x + e1.y * w1.y + e1.z * w1.z + e1.w * w1.w;
    g_H[idx] = fmaxf(h, 0.0f);
}

// ---------------------------------------------------------------------------
// Kernel 3: transpose W2 [EMB, FFN] -> W2T [FFN, EMB] for coalesced GEMM B
// ---------------------------------------------------------------------------
__global__ void transpose_kernel(const float* __restrict__ W2) {
    __shared__ float tile[32][33];
    int kbase = blockIdx.x * 32;   // FFN dim
    int nbase = blockIdx.y * 32;   // EMB dim
    int tx = threadIdx.x, ty = threadIdx.y;  // block (32, 8)
#pragma unroll
    for (int i = 0; i < 32; i += 8)
        tile[ty + i][tx] = W2[(size_t)(nbase + ty + i) * FFN + kbase + tx];
    __syncthreads();
#pragma unroll
    for (int i = 0; i < 32; i += 8)
        g_W2T[(size_t)(kbase + ty + i) * EMB + nbase + tx] = tile[tx][ty + i];
}

// ---------------------------------------------------------------------------
// Kernel 4: OUT[M,N] = H[M,K] @ W2T[K,N] + b2
// 128x128 block tile, BK=8, 256 threads, 8x8 per-thread, global prefetch.
// ---------------------------------------------------------------------------
__global__ void __launch_bounds__(256)
sgemm_kernel(const float* __restrict__ bias, float* __restrict__ C) {
    const int K = FFN, N = EMB;
    __shared__ __align__(16) float As[8][128];
    __shared__ __align__(16) float Bs[8][128];

    int tid = threadIdx.x;
    int bm = blockIdx.y * 128;
    int bn = blockIdx.x * 128;
    int tx = tid & 15;          // 16 thread cols
    int ty = tid >> 4;          // 16 thread rows

    // Global-load assignments: 256 float4 per tile each for A and B
    int aRow = tid >> 1;              // 0..127
    int aK   = (tid & 1) << 2;        // 0 or 4
    int bK   = tid >> 5;              // 0..7
    int bCol = (tid & 31) << 2;       // 0..124

    const float* Aptr = g_H   + (size_t)(bm + aRow) * K + aK;
    const float* Bptr = g_W2T + (size_t)bK * N + bn + bCol;

    float acc[8][8];
#pragma unroll
    for (int i = 0; i < 8; i++)
#pragma unroll
        for (int j = 0; j < 8; j++) acc[i][j] = 0.0f;

    float4 av = *(const float4*)Aptr;
    float4 bv = *(const float4*)Bptr;

    for (int k0 = 0; k0 < K; k0 += 8) {
        As[aK + 0][aRow] = av.x;
        As[aK + 1][aRow] = av.y;
        As[aK + 2][aRow] = av.z;
        As[aK + 3][aRow] = av.w;
        *(float4*)&Bs[bK][bCol] = bv;
        __syncthreads();

        if (k0 + 8 < K) {          // prefetch next tile while computing
            Aptr += 8;
            Bptr += 8 * N;
            av = *(const float4*)Aptr;
            bv = *(const float4*)Bptr;
        }

#pragma unroll
        for (int kk = 0; kk < 8; kk++) {
            float4 a0 = *(const float4*)&As[kk][ty * 8];
            float4 a1 = *(const float4*)&As[kk][ty * 8 + 4];
            float4 b0 = *(const float4*)&Bs[kk][tx * 8];
            float4 b1 = *(const float4*)&Bs[kk][tx * 8 + 4];
            float ra[8] = {a0.x, a0.y, a0.z, a0.w, a1.x, a1.y, a1.z, a1.w};
            float rb[8] = {b0.x, b0.y, b0.z, b0.w, b1.x, b1.y, b1.z, b1.w};
#pragma unroll
            for (int i = 0; i < 8; i++)
#pragma unroll
                for (int j = 0; j < 8; j++)
                    acc[i][j] += ra[i] * rb[j];
        }
        __syncthreads();
    }

#pragma unroll
    for (int i = 0; i < 8; i++) {
        int m = bm + ty * 8 + i;
#pragma unroll
        for (int j = 0; j < 8; j += 4) {
            int n = bn + tx * 8 + j;
            float4 o;
            o.x = acc[i][j + 0] + bias[n + 0];
            o.y = acc[i][j + 1] + bias[n + 1];
            o.z = acc[i][j + 2] + bias[n + 2];
            o.w = acc[i][j + 3] + bias[n + 3];
            *(float4*)&C[(size_t)m * N + n] = o;
        }
    }
}

// ---------------------------------------------------------------------------
extern "C" void kernel_launch(void* const* d_in, const int* in_sizes, int n_in,
                              void* d_out, int out_size) {
    const float* x      = (const float*)d_in[0];  // [16,2048,8]
    const float* params = (const float*)d_in[1];  // [8,3]
    const float* W1     = (const float*)d_in[2];  // [2048,8]
    const float* b1     = (const float*)d_in[3];  // [2048]
    const float* W2     = (const float*)d_in[4];  // [512,2048]
    const float* b2     = (const float*)d_in[5];  // [512]
    float* out = (float*)d_out;                   // [16,2048,512]

    ev_kernel<<<NROWS / 256, 256>>>(x, params);
    h_kernel<<<(NROWS * FFN) / 256, 256>>>(W1, b1);
    transpose_kernel<<<dim3(FFN / 32, EMB / 32), dim3(32, 8)>>>(W2);
    sgemm_kernel<<<dim3(EMB / 128, NROWS / 128), 256>>>(b2, out);
}

// round 2
// speedup vs baseline: 2.1086x; 2.1086x over previous
#include <cuda_runtime.h>
#include <cuda_bf16.h>
#include <math.h>

#define NROWS 32768      // B*S
#define FFN   2048
#define EMB   512

// ---------------- scratch (static device globals per allocation rules) -----
__device__ float         g_EV[NROWS * 8];                       // 1 MB
__device__ __nv_bfloat16 g_Hh[(size_t)NROWS * FFN];             // 128 MB
__device__ __nv_bfloat16 g_Hl[(size_t)NROWS * FFN];             // 128 MB
__device__ __nv_bfloat16 g_Wh[EMB * FFN];                       // 2 MB
__device__ __nv_bfloat16 g_Wl[EMB * FFN];                       // 2 MB

// ---------------------------------------------------------------------------
// Kernel 1: quantum circuit collapsed to closed form (verified R1).
// z_i = A_i cos x_i - C_i sin x_i ; ev_0 = z1..z7, ev_k = z0..zk (k>=1)
// ---------------------------------------------------------------------------
__global__ void ev_kernel(const float* __restrict__ x,
                          const float* __restrict__ params) {
    int row = blockIdx.x * blockDim.x + threadIdx.x;
    if (row >= NROWS) return;
    float z[8];
#pragma unroll
    for (int i = 0; i < 8; i++) {
        float a = params[i * 3 + 0];
        float b = params[i * 3 + 1];
        float c = params[i * 3 + 2];
        float sa, ca, sb, cb, sc, cc;
        sincosf(a, &sa, &ca);
        sincosf(b, &sb, &cb);
        sincosf(c, &sc, &cc);
        float Acoef = ca * cc + sa * sb * sc;
        float Ccoef = cb * sc;
        float sx, cx;
        sincosf(x[row * 8 + i], &sx, &cx);
        z[i] = Acoef * cx - Ccoef * sx;
    }
    float ev[8];
    float pre = z[0];
#pragma unroll
    for (int k = 1; k < 8; k++) { pre *= z[k]; ev[k] = pre; }
    float suf = 1.0f;
#pragma unroll
    for (int k = 7; k >= 1; k--) suf *= z[k];
    ev[0] = suf;
    float4* out = (float4*)&g_EV[row * 8];
    out[0] = make_float4(ev[0], ev[1], ev[2], ev[3]);
    out[1] = make_float4(ev[4], ev[5], ev[6], ev[7]);
}

// ---------------------------------------------------------------------------
// Kernel 2: H = relu(EV @ W1^T + b1), written directly as split bf16 (hi+lo)
// ---------------------------------------------------------------------------
__global__ void h_split_kernel(const float* __restrict__ W1,
                               const float* __restrict__ b1) {
    int idx = blockIdx.x * blockDim.x + threadIdx.x;   // [0, NROWS*FFN/2)
    int row = idx >> 10;                 // FFN/2 = 1024 pairs per row
    int c   = (idx & 1023) << 1;
    const float4* e = (const float4*)&g_EV[row * 8];
    float4 e0 = e[0], e1 = e[1];
    float hv[2];
#pragma unroll
    for (int j = 0; j < 2; j++) {
        const float4* w = (const float4*)&W1[(c + j) * 8];
        float4 w0 = w[0], w1 = w[1];
        float h = b1[c + j]
                + e0.x * w0.x + e0.y * w0.y + e0.z * w0.z + e0.w * w0.w
                + e1.x * w1.x + e1.y * w1.y + e1.z * w1.z + e1.w * w1.w;
        hv[j] = fmaxf(h, 0.0f);
    }
    __nv_bfloat16 h0 = __float2bfloat16(hv[0]);
    __nv_bfloat16 h1 = __float2bfloat16(hv[1]);
    __nv_bfloat16 l0 = __float2bfloat16(hv[0] - __bfloat162float(h0));
    __nv_bfloat16 l1 = __float2bfloat16(hv[1] - __bfloat162float(h1));
    ((__nv_bfloat162*)g_Hh)[idx] = __halves2bfloat162(h0, h1);
    ((__nv_bfloat162*)g_Hl)[idx] = __halves2bfloat162(l0, l1);
}

// ---------------------------------------------------------------------------
// Kernel 3: split W2 [EMB, FFN] (already the [N,K] layout mma's B wants)
// ---------------------------------------------------------------------------
__global__ void w_split_kernel(const float* __restrict__ W2) {
    int idx = blockIdx.x * blockDim.x + threadIdx.x;   // [0, EMB*FFN/2)
    float2 v = ((const float2*)W2)[idx];
    __nv_bfloat16 h0 = __float2bfloat16(v.x);
    __nv_bfloat16 h1 = __float2bfloat16(v.y);
    __nv_bfloat16 l0 = __float2bfloat16(v.x - __bfloat162float(h0));
    __nv_bfloat16 l1 = __float2bfloat16(v.y - __bfloat162float(h1));
    ((__nv_bfloat162*)g_Wh)[idx] = __halves2bfloat162(h0, h1);
    ((__nv_bfloat162*)g_Wl)[idx] = __halves2bfloat162(l0, l1);
}

// ---------------------------------------------------------------------------
// Kernel 4: OUT = H @ W2^T + b2 via mma.sync bf16 split-precision (3 passes)
// CTA 128x64x32, 8 warps (4x2, warp tile 32x32), double-buffered cp.async,
// XOR-swizzled smem (conflict-free ldmatrix), 48KB static smem, 2 CTAs/SM.
// ---------------------------------------------------------------------------
#define BM 128
#define BN 64
#define BK 32
// stage layout (bytes): Ah 0, Al 8192, Bh 16384, Bl 20480 ; stage = 24576

#define CP_ASYNC(dst, src) \
    asm volatile("cp.async.cg.shared.global [%0], [%1], 16;\n" :: "r"(dst), "l"(src))

__device__ __forceinline__ void ldsm4(unsigned* r, unsigned a) {
    asm volatile("ldmatrix.sync.aligned.m8n8.x4.shared.b16 {%0,%1,%2,%3}, [%4];"
                 : "=r"(r[0]), "=r"(r[1]), "=r"(r[2]), "=r"(r[3]) : "r"(a));
}

__device__ __forceinline__ void mma16816(float* c, const unsigned* a, const unsigned* b) {
    asm volatile("mma.sync.aligned.m16n8k16.row.col.f32.bf16.bf16.f32 "
                 "{%0,%1,%2,%3}, {%4,%5,%6,%7}, {%8,%9}, {%0,%1,%2,%3};"
                 : "+f"(c[0]), "+f"(c[1]), "+f"(c[2]), "+f"(c[3])
                 : "r"(a[0]), "r"(a[1]), "r"(a[2]), "r"(a[3]), "r"(b[0]), "r"(b[1]));
}

__device__ __forceinline__ unsigned swz(int row, int ch) {  // byte offset, 64B rows
    return (unsigned)(row * 64 + ((ch ^ ((row >> 1) & 3)) << 4));
}

__device__ __forceinline__ void load_stage(unsigned st, int bm, int bn, int tid, int k0) {
#pragma unroll
    for (int i = 0; i < 2; i++) {               // A: 512 chunks of 16B
        int c = tid + (i << 8);
        int r = c >> 2, ch = c & 3;
        unsigned soff = swz(r, ch);
        size_t g = (size_t)(bm + r) * FFN + k0 + ch * 8;
        CP_ASYNC(st + soff,        g_Hh + g);
        CP_ASYNC(st + 8192 + soff, g_Hl + g);
    }
    {                                           // B: 256 chunks of 16B
        int r = tid >> 2, ch = tid & 3;
        unsigned soff = swz(r, ch);
        size_t g = (size_t)(bn + r) * FFN + k0 + ch * 8;
        CP_ASYNC(st + 16384 + soff, g_Wh + g);
        CP_ASYNC(st + 20480 + soff, g_Wl + g);
    }
}

__global__ void __launch_bounds__(256, 2)
mma_gemm(const float* __restrict__ bias, float* __restrict__ C) {
    __shared__ __align__(16) unsigned char smem[2 * 24576];
    const int tid  = threadIdx.x;
    const int warp = tid >> 5, lane = tid & 31;
    const int wm = warp & 3, wn = warp >> 2;
    const int bm = blockIdx.y * BM, bn = blockIdx.x * BN;
    const unsigned sbase = (unsigned)__cvta_generic_to_shared(smem);

    float acc[2][4][4];
#pragma unroll
    for (int i = 0; i < 2; i++)
#pragma unroll
        for (int j = 0; j < 4; j++)
#pragma unroll
            for (int k = 0; k < 4; k++) acc[i][j][k] = 0.0f;

    load_stage(sbase, bm, bn, tid, 0);
    asm volatile("cp.async.commit_group;\n");

    const int NT = FFN / BK;   // 64
    for (int t = 0; t < NT; t++) {
        if (t + 1 < NT) {
            load_stage(sbase + ((t + 1) & 1) * 24576, bm, bn, tid, (t + 1) * BK);
            asm volatile("cp.async.commit_group;\n");
            asm volatile("cp.async.wait_group 1;\n");
        } else {
            asm volatile("cp.async.wait_group 0;\n");
        }
        __syncthreads();

        unsigned st = sbase + (t & 1) * 24576;
#pragma unroll
        for (int kk = 0; kk < 2; kk++) {         // two k16 halves of BK=32
            unsigned ah[2][4], al[2][4], bh[2][4], bl[2][4];
#pragma unroll
            for (int mf = 0; mf < 2; mf++) {     // A fragments (16x16)
                int r  = wm * 32 + mf * 16 + (lane & 15);
                int ch = kk * 2 + (lane >> 4);
                unsigned a = st + swz(r, ch);
                ldsm4(ah[mf], a);
                ldsm4(al[mf], a + 8192);
            }
#pragma unroll
            for (int nb = 0; nb < 2; nb++) {     // B fragments (2x n8 per ldsm4)
                int n  = wn * 32 + nb * 16 + (lane & 7) + ((lane >> 4) & 1) * 8;
                int ch = kk * 2 + ((lane >> 3) & 1);
                unsigned a = st + 16384 + swz(n, ch);
                ldsm4(bh[nb], a);
                ldsm4(bl[nb], a + 4096);
            }
#pragma unroll
            for (int mf = 0; mf < 2; mf++)
#pragma unroll
                for (int nf = 0; nf < 4; nf++) {
                    const unsigned* bhp = &bh[nf >> 1][(nf & 1) * 2];
                    const unsigned* blp = &bl[nf >> 1][(nf & 1) * 2];
                    mma16816(acc[mf][nf], ah[mf], bhp);   // Ah*Bh
                    mma16816(acc[mf][nf], al[mf], bhp);   // Al*Bh
                    mma16816(acc[mf][nf], ah[mf], blp);   // Ah*Bl
                }
        }
        __syncthreads();
    }

    // epilogue: acc layout m16n8 -> c0,c1: (row=lane/4, col=2*(lane%4)+{0,1}); c2,c3: row+8
#pragma unroll
    for (int mf = 0; mf < 2; mf++) {
        int r0 = bm + wm * 32 + mf * 16 + (lane >> 2);
#pragma unroll
        for (int nf = 0; nf < 4; nf++) {
            int cc = bn + wn * 32 + nf * 8 + (lane & 3) * 2;
            float2 b2 = *(const float2*)&bias[cc];
            float2 v0 = make_float2(acc[mf][nf][0] + b2.x, acc[mf][nf][1] + b2.y);
            float2 v1 = make_float2(acc[mf][nf][2] + b2.x, acc[mf][nf][3] + b2.y);
            *(float2*)&C[(size_t)r0 * EMB + cc]       = v0;
            *(float2*)&C[(size_t)(r0 + 8) * EMB + cc] = v1;
        }
    }
}

// ---------------------------------------------------------------------------
extern "C" void kernel_launch(void* const* d_in, const int* in_sizes, int n_in,
                              void* d_out, int out_size) {
    const float* x      = (const float*)d_in[0];  // [16,2048,8]
    const float* params = (const float*)d_in[1];  // [8,3]
    const float* W1     = (const float*)d_in[2];  // [2048,8]
    const float* b1     = (const float*)d_in[3];  // [2048]
    const float* W2     = (const float*)d_in[4];  // [512,2048]
    const float* b2     = (const float*)d_in[5];  // [512]
    float* out = (float*)d_out;                   // [16,2048,512]

    ev_kernel<<<NROWS / 256, 256>>>(x, params);
    h_split_kernel<<<(NROWS * (FFN / 2)) / 256, 256>>>(W1, b1);
    w_split_kernel<<<(EMB * (FFN / 2)) / 256, 256>>>(W2);
    mma_gemm<<<dim3(EMB / BN, NROWS / BM), 256>>>(b2, out);
}